// round 5
// baseline (speedup 1.0000x reference)
#include <cuda_runtime.h>
#include <cuda_fp16.h>
#include <cstdint>

// Round 2: A fragments register-resident (loaded once per GEMM group instead of
// per chunk), B fragments packed as uint4 (LDG.128). M=64 tile, 8 warps,
// warp = 16 rows x 32 cols, 2 CTAs/SM.

#define NHEADS 4
#define SEQT   8
#define DM     256
#define DH     64
#define MT     64
#define AROW   264                  // halves per row of Xs/Os (256+8 pad)
#define SROW   68                   // halves per row of qkv staging
#define STG_STRIDE (MT * SROW)
#define XS_HALVES  (MT * AROW)
#define STG_OFF    XS_HALVES
#define OS_OFF     (XS_HALVES + 3 * STG_STRIDE)
#define SMEM_HALVES (OS_OFF + MT * AROW)
#define SMEM_BYTES  (SMEM_HALVES * 2)   // 93696 B

// 16 chunks (12 QKV: cid=h*3+part; 4 FC: cid=12+nc), each [N=64, K=256].
// uint4 layout: [cid][kt(16)][j(4)][lane(32)], j = nt-pair; uint4 =
// {nt=2j: reg0, reg1, nt=2j+1: reg0, reg1} of mma m16n8k16 B fragments.
__device__ uint4 g_frag4[16 * 16 * 4 * 32];   // 512 KB

__global__ void prep_frags(const float* __restrict__ Wq, const float* __restrict__ Wk,
                           const float* __restrict__ Wv, const float* __restrict__ Wfc) {
    int g = blockIdx.x * 256 + threadIdx.x;          // 32768 threads
    int lane = g & 31, j = (g >> 5) & 3, kt = (g >> 7) & 15, cid = g >> 11;
    int n0 = j * 16 + (lane >> 2);                   // col of nt=2j
    int k0 = kt * 16 + ((lane & 3) << 1);
    float a0, a1, a2, a3, c0, c1, c2, c3;
    if (cid < 12) {
        int h = cid / 3, part = cid % 3;
        const float* W = (part == 0) ? Wq : ((part == 1) ? Wk : Wv);
        const float* p = W + h * DM * DH + n0;       // W[h][k][n], n-stride 1, k-stride DH
        a0 = p[k0 * DH];       a1 = p[(k0 + 1) * DH];
        a2 = p[(k0 + 8) * DH]; a3 = p[(k0 + 9) * DH];
        p += 8;
        c0 = p[k0 * DH];       c1 = p[(k0 + 1) * DH];
        c2 = p[(k0 + 8) * DH]; c3 = p[(k0 + 9) * DH];
    } else {
        int nc = cid - 12;
        const float* p = Wfc + nc * 64 + n0;         // Wfc[k][n], n-stride 1, k-stride 256
        a0 = p[k0 * 256];       a1 = p[(k0 + 1) * 256];
        a2 = p[(k0 + 8) * 256]; a3 = p[(k0 + 9) * 256];
        p += 8;
        c0 = p[k0 * 256];       c1 = p[(k0 + 1) * 256];
        c2 = p[(k0 + 8) * 256]; c3 = p[(k0 + 9) * 256];
    }
    __half2 l0 = __floats2half2_rn(a0, a1), h0 = __floats2half2_rn(a2, a3);
    __half2 l1 = __floats2half2_rn(c0, c1), h1 = __floats2half2_rn(c2, c3);
    uint4 v;
    v.x = *reinterpret_cast<uint32_t*>(&l0);
    v.y = *reinterpret_cast<uint32_t*>(&h0);
    v.z = *reinterpret_cast<uint32_t*>(&l1);
    v.w = *reinterpret_cast<uint32_t*>(&h1);
    g_frag4[g] = v;
}

#define LDSM4(R0, R1, R2, R3, ADDR)                                                \
    asm volatile("ldmatrix.sync.aligned.m8n8.x4.shared.b16 {%0,%1,%2,%3}, [%4];\n" \
                 : "=r"(R0), "=r"(R1), "=r"(R2), "=r"(R3)                          \
                 : "r"(ADDR))

#define MMA16816(D, A0, A1, A2, A3, B0, B1)                                        \
    asm volatile(                                                                  \
        "mma.sync.aligned.m16n8k16.row.col.f32.f16.f16.f32 "                       \
        "{%0,%1,%2,%3}, {%4,%5,%6,%7}, {%8,%9}, {%0,%1,%2,%3};\n"                  \
        : "+f"(D[0]), "+f"(D[1]), "+f"(D[2]), "+f"(D[3])                           \
        : "r"(A0), "r"(A1), "r"(A2), "r"(A3), "r"(B0), "r"(B1))

// Load warp's A fragments (16 rows x K=256) into registers: a[16][4].
__device__ __forceinline__ void load_afrag(const __half* A, int wm, int lane,
                                           uint32_t a[16][4]) {
    uint32_t Abase = (uint32_t)__cvta_generic_to_shared(A);
    int arow = (((lane >> 3) & 1) << 3) + (lane & 7);
    int ak   = (lane >> 4) << 3;
    uint32_t addr0 = Abase + (uint32_t)(((wm + arow) * AROW + ak) * 2);
#pragma unroll
    for (int kt = 0; kt < 16; ++kt)
        LDSM4(a[kt][0], a[kt][1], a[kt][2], a[kt][3], addr0 + (uint32_t)(kt * 32));
}

// C[16x32] per warp for chunk cid, A from regs, B via LDG.128.
__device__ __forceinline__ void gemm_reg(const uint32_t a[16][4], int cid,
                                         int wn, int lane, float acc[4][4]) {
    const uint4* frag = g_frag4 + (cid * 64 + (wn >> 4)) * 32 + lane;
#pragma unroll
    for (int kt = 0; kt < 16; ++kt) {
        uint4 B01 = frag[(kt * 4) * 32];
        uint4 B23 = frag[(kt * 4 + 1) * 32];
        MMA16816(acc[0], a[kt][0], a[kt][1], a[kt][2], a[kt][3], B01.x, B01.y);
        MMA16816(acc[1], a[kt][0], a[kt][1], a[kt][2], a[kt][3], B01.z, B01.w);
        MMA16816(acc[2], a[kt][0], a[kt][1], a[kt][2], a[kt][3], B23.x, B23.y);
        MMA16816(acc[3], a[kt][0], a[kt][1], a[kt][2], a[kt][3], B23.z, B23.w);
    }
}

__global__ __launch_bounds__(256, 2)
void attn_main(const float* __restrict__ x, const float* __restrict__ bq,
               const float* __restrict__ bk, const float* __restrict__ bv,
               const float* __restrict__ bfc, float* __restrict__ out) {
    extern __shared__ __half sm[];
    __half* Xs  = sm;             // [64][AROW]
    __half* Stg = sm + STG_OFF;   // 3 x [64][SROW]
    __half* Os  = sm + OS_OFF;    // [64][AROW]

    int tid = threadIdx.x, lane = tid & 31, wid = tid >> 5;
    int wm = (wid >> 1) * 16;     // 0,16,32,48
    int wn = (wid & 1) * 32;      // 0,32
    int row0 = blockIdx.x * MT;

    // ---- X tile: fp32 -> fp16 smem ----
#pragma unroll
    for (int i = tid; i < MT * 64; i += 256) {
        int r = i >> 6, c4 = i & 63;
        float4 v = reinterpret_cast<const float4*>(x)[(row0 + r) * 64 + c4];
        __half2* d = reinterpret_cast<__half2*>(Xs + r * AROW + c4 * 4);
        d[0] = __floats2half2_rn(v.x, v.y);
        d[1] = __floats2half2_rn(v.z, v.w);
    }
    __syncthreads();

    uint32_t a[16][4];
    load_afrag(Xs, wm, lane, a);   // A fragments live across all QKV chunks

    for (int h = 0; h < NHEADS; ++h) {
#pragma unroll
        for (int part = 0; part < 3; ++part) {
            float acc[4][4];
#pragma unroll
            for (int ni = 0; ni < 4; ++ni)
#pragma unroll
                for (int c = 0; c < 4; ++c) acc[ni][c] = 0.f;
            gemm_reg(a, h * 3 + part, wn, lane, acc);

            const float* pb = (part == 0) ? bq : ((part == 1) ? bk : bv);
            __half* S = Stg + part * STG_STRIDE;
            int r = wm + (lane >> 2);
            int cb = wn + ((lane & 3) << 1);
#pragma unroll
            for (int ni = 0; ni < 4; ++ni) {
                int c = cb + ni * 8;
                float b0 = pb[h * DH + c], b1 = pb[h * DH + c + 1];
                *reinterpret_cast<__half2*>(S + r * SROW + c) =
                    __floats2half2_rn(acc[ni][0] + b0, acc[ni][1] + b1);
                *reinterpret_cast<__half2*>(S + (r + 8) * SROW + c) =
                    __floats2half2_rn(acc[ni][2] + b0, acc[ni][3] + b1);
            }
        }
        __syncthreads();

        // ---- attention: 4 threads per row ----
        {
            int row = tid >> 2, qtr = tid & 3;
            int base = row & ~7, t = row & 7;
            const __half2* qp = reinterpret_cast<const __half2*>(Stg + row * SROW) + qtr * 8;
            __half2 q2[8];
#pragma unroll
            for (int j = 0; j < 8; ++j) q2[j] = qp[j];

            float sc[SEQT];
#pragma unroll
            for (int s = 0; s < SEQT; ++s) {
                const __half2* kp =
                    reinterpret_cast<const __half2*>(Stg + STG_STRIDE + (base + s) * SROW) + qtr * 8;
                float acl = 0.f;
#pragma unroll
                for (int j = 0; j < 8; ++j) {
                    __half2 p = __hmul2(q2[j], kp[j]);
                    acl += __low2float(p) + __high2float(p);
                }
                acl += __shfl_xor_sync(0xffffffffu, acl, 1);
                acl += __shfl_xor_sync(0xffffffffu, acl, 2);
                sc[s] = acl * 0.125f;   // 1/sqrt(64)
            }
            float m = sc[0];
#pragma unroll
            for (int s = 1; s < SEQT; ++s)
                if (s <= t && sc[s] > m) m = sc[s];
            float w[SEQT], sum = 0.f;
#pragma unroll
            for (int s = 0; s < SEQT; ++s) {
                w[s] = (s <= t) ? __expf(sc[s] - m) : 0.f;
                sum += w[s];
            }
            float inv = 1.f / sum;
            float o[16];
#pragma unroll
            for (int j = 0; j < 16; ++j) o[j] = 0.f;
#pragma unroll
            for (int s = 0; s < SEQT; ++s) {
                float ws = w[s] * inv;
                const __half2* vp =
                    reinterpret_cast<const __half2*>(Stg + 2 * STG_STRIDE + (base + s) * SROW) + qtr * 8;
#pragma unroll
                for (int j = 0; j < 8; ++j) {
                    __half2 v2 = vp[j];
                    o[2 * j]     += ws * __low2float(v2);
                    o[2 * j + 1] += ws * __high2float(v2);
                }
            }
            __half2* op = reinterpret_cast<__half2*>(Os + row * AROW + h * DH + qtr * 16);
#pragma unroll
            for (int j = 0; j < 8; ++j) op[j] = __floats2half2_rn(o[2 * j], o[2 * j + 1]);
        }
        __syncthreads();
    }

    // ---- output projection: Os[64,256] @ Wfc + bfc -> out (fp32) ----
    load_afrag(Os, wm, lane, a);   // reuse register array for Os fragments
#pragma unroll
    for (int nc = 0; nc < 4; ++nc) {
        float acc[4][4];
#pragma unroll
        for (int ni = 0; ni < 4; ++ni)
#pragma unroll
            for (int c = 0; c < 4; ++c) acc[ni][c] = 0.f;
        gemm_reg(a, 12 + nc, wn, lane, acc);

        int r = wm + (lane >> 2);
        int cb = nc * 64 + wn + ((lane & 3) << 1);
#pragma unroll
        for (int ni = 0; ni < 4; ++ni) {
            int c = cb + ni * 8;
            float b0 = bfc[c], b1 = bfc[c + 1];
            *reinterpret_cast<float2*>(out + (row0 + r) * 256 + c) =
                make_float2(acc[ni][0] + b0, acc[ni][1] + b1);
            *reinterpret_cast<float2*>(out + (row0 + r + 8) * 256 + c) =
                make_float2(acc[ni][2] + b0, acc[ni][3] + b1);
        }
    }
}

extern "C" void kernel_launch(void* const* d_in, const int* in_sizes, int n_in,
                              void* d_out, int out_size) {
    (void)in_sizes; (void)n_in; (void)out_size;
    const float* x   = (const float*)d_in[0];
    const float* Wq  = (const float*)d_in[1];
    const float* bq  = (const float*)d_in[2];
    const float* Wk  = (const float*)d_in[3];
    const float* bk  = (const float*)d_in[4];
    const float* Wv  = (const float*)d_in[5];
    const float* bv  = (const float*)d_in[6];
    const float* Wfc = (const float*)d_in[7];
    const float* bfc = (const float*)d_in[8];
    float* out = (float*)d_out;

    cudaFuncSetAttribute(attn_main, cudaFuncAttributeMaxDynamicSharedMemorySize, SMEM_BYTES);

    prep_frags<<<128, 256>>>(Wq, Wk, Wv, Wfc);
    attn_main<<<4096, 256, SMEM_BYTES>>>(x, bq, bk, bv, bfc, out);
}

// round 9
// speedup vs baseline: 1.0300x; 1.0300x over previous
#include <cuda_runtime.h>
#include <cuda_fp16.h>
#include <cstdint>

// Round 7 (= round 5 resubmit after infra failure): R1 structure + per-head-
// scoped A-fragment hoisting (no liveness across attention -> no spills) +
// uint4-packed B fragments (LDG.128). M=64 tile, 8 warps (warp = 16 rows x
// 32 cols), 2 CTAs/SM.

#define NHEADS 4
#define SEQT   8
#define DM     256
#define DH     64
#define MT     64
#define AROW   264                  // halves per row of Xs/Os (256+8 pad)
#define SROW   68                   // halves per row of qkv staging
#define STG_STRIDE (MT * SROW)
#define XS_HALVES  (MT * AROW)
#define STG_OFF    XS_HALVES
#define OS_OFF     (XS_HALVES + 3 * STG_STRIDE)
#define SMEM_HALVES (OS_OFF + MT * AROW)
#define SMEM_BYTES  (SMEM_HALVES * 2)   // 93696 B

// 16 chunks (12 QKV: cid=h*3+part; 4 FC: cid=12+nc), each [N=64, K=256].
// uint4 layout: [cid][kt(16)][j(4)][lane(32)], j = nt-pair; uint4 =
// {nt=2j: reg0, reg1, nt=2j+1: reg0, reg1} of mma m16n8k16 B fragments.
__device__ uint4 g_frag4[16 * 16 * 4 * 32];   // 512 KB

__global__ void prep_frags(const float* __restrict__ Wq, const float* __restrict__ Wk,
                           const float* __restrict__ Wv, const float* __restrict__ Wfc) {
    int g = blockIdx.x * 256 + threadIdx.x;          // 32768 threads
    int lane = g & 31, j = (g >> 5) & 3, kt = (g >> 7) & 15, cid = g >> 11;
    int n0 = j * 16 + (lane >> 2);                   // col of nt=2j
    int k0 = kt * 16 + ((lane & 3) << 1);
    float a0, a1, a2, a3, c0, c1, c2, c3;
    if (cid < 12) {
        int h = cid / 3, part = cid % 3;
        const float* W = (part == 0) ? Wq : ((part == 1) ? Wk : Wv);
        const float* p = W + h * DM * DH + n0;       // W[h][k][n], n-stride 1, k-stride DH
        a0 = p[k0 * DH];       a1 = p[(k0 + 1) * DH];
        a2 = p[(k0 + 8) * DH]; a3 = p[(k0 + 9) * DH];
        p += 8;
        c0 = p[k0 * DH];       c1 = p[(k0 + 1) * DH];
        c2 = p[(k0 + 8) * DH]; c3 = p[(k0 + 9) * DH];
    } else {
        int nc = cid - 12;
        const float* p = Wfc + nc * 64 + n0;         // Wfc[k][n], n-stride 1, k-stride 256
        a0 = p[k0 * 256];       a1 = p[(k0 + 1) * 256];
        a2 = p[(k0 + 8) * 256]; a3 = p[(k0 + 9) * 256];
        p += 8;
        c0 = p[k0 * 256];       c1 = p[(k0 + 1) * 256];
        c2 = p[(k0 + 8) * 256]; c3 = p[(k0 + 9) * 256];
    }
    __half2 l0 = __floats2half2_rn(a0, a1), h0 = __floats2half2_rn(a2, a3);
    __half2 l1 = __floats2half2_rn(c0, c1), h1 = __floats2half2_rn(c2, c3);
    uint4 v;
    v.x = *reinterpret_cast<uint32_t*>(&l0);
    v.y = *reinterpret_cast<uint32_t*>(&h0);
    v.z = *reinterpret_cast<uint32_t*>(&l1);
    v.w = *reinterpret_cast<uint32_t*>(&h1);
    g_frag4[g] = v;
}

#define LDSM4(R0, R1, R2, R3, ADDR)                                                \
    asm volatile("ldmatrix.sync.aligned.m8n8.x4.shared.b16 {%0,%1,%2,%3}, [%4];\n" \
                 : "=r"(R0), "=r"(R1), "=r"(R2), "=r"(R3)                          \
                 : "r"(ADDR))

#define MMA16816(D, A0, A1, A2, A3, B0, B1)                                        \
    asm volatile(                                                                  \
        "mma.sync.aligned.m16n8k16.row.col.f32.f16.f16.f32 "                       \
        "{%0,%1,%2,%3}, {%4,%5,%6,%7}, {%8,%9}, {%0,%1,%2,%3};\n"                  \
        : "+f"(D[0]), "+f"(D[1]), "+f"(D[2]), "+f"(D[3])                           \
        : "r"(A0), "r"(A1), "r"(A2), "r"(A3), "r"(B0), "r"(B1))

// Load warp's A fragments (16 rows x K=256) into registers: a[16][4].
__device__ __forceinline__ void load_afrag(const __half* A, int wm, int lane,
                                           uint32_t a[16][4]) {
    uint32_t Abase = (uint32_t)__cvta_generic_to_shared(A);
    int arow = (((lane >> 3) & 1) << 3) + (lane & 7);
    int ak   = (lane >> 4) << 3;
    uint32_t addr0 = Abase + (uint32_t)(((wm + arow) * AROW + ak) * 2);
#pragma unroll
    for (int kt = 0; kt < 16; ++kt)
        LDSM4(a[kt][0], a[kt][1], a[kt][2], a[kt][3], addr0 + (uint32_t)(kt * 32));
}

// C[16x32] per warp for chunk cid, A from regs, B via LDG.128.
__device__ __forceinline__ void gemm_reg(const uint32_t a[16][4], int cid,
                                         int wn, int lane, float acc[4][4]) {
    const uint4* frag = g_frag4 + (cid * 64 + (wn >> 4)) * 32 + lane;
#pragma unroll
    for (int kt = 0; kt < 16; ++kt) {
        uint4 B01 = frag[(kt * 4) * 32];
        uint4 B23 = frag[(kt * 4 + 1) * 32];
        MMA16816(acc[0], a[kt][0], a[kt][1], a[kt][2], a[kt][3], B01.x, B01.y);
        MMA16816(acc[1], a[kt][0], a[kt][1], a[kt][2], a[kt][3], B01.z, B01.w);
        MMA16816(acc[2], a[kt][0], a[kt][1], a[kt][2], a[kt][3], B23.x, B23.y);
        MMA16816(acc[3], a[kt][0], a[kt][1], a[kt][2], a[kt][3], B23.z, B23.w);
    }
}

__global__ __launch_bounds__(256, 2)
void attn_main(const float* __restrict__ x, const float* __restrict__ bq,
               const float* __restrict__ bk, const float* __restrict__ bv,
               const float* __restrict__ bfc, float* __restrict__ out) {
    extern __shared__ __half sm[];
    __half* Xs  = sm;             // [64][AROW]
    __half* Stg = sm + STG_OFF;   // 3 x [64][SROW]
    __half* Os  = sm + OS_OFF;    // [64][AROW]

    int tid = threadIdx.x, lane = tid & 31, wid = tid >> 5;
    int wm = (wid >> 1) * 16;     // 0,16,32,48
    int wn = (wid & 1) * 32;      // 0,32
    int row0 = blockIdx.x * MT;

    // ---- X tile: fp32 -> fp16 smem ----
#pragma unroll
    for (int i = tid; i < MT * 64; i += 256) {
        int r = i >> 6, c4 = i & 63;
        float4 v = reinterpret_cast<const float4*>(x)[(row0 + r) * 64 + c4];
        __half2* d = reinterpret_cast<__half2*>(Xs + r * AROW + c4 * 4);
        d[0] = __floats2half2_rn(v.x, v.y);
        d[1] = __floats2half2_rn(v.z, v.w);
    }
    __syncthreads();

    for (int h = 0; h < NHEADS; ++h) {
        {
            // A fragments: scoped to this head's QKV GEMMs only (dead during
            // attention -> no spills; asm volatile LDSM forces the reload).
            uint32_t a[16][4];
            load_afrag(Xs, wm, lane, a);
#pragma unroll
            for (int part = 0; part < 3; ++part) {
                float acc[4][4];
#pragma unroll
                for (int ni = 0; ni < 4; ++ni)
#pragma unroll
                    for (int c = 0; c < 4; ++c) acc[ni][c] = 0.f;
                gemm_reg(a, h * 3 + part, wn, lane, acc);

                const float* pb = (part == 0) ? bq : ((part == 1) ? bk : bv);
                __half* S = Stg + part * STG_STRIDE;
                int r = wm + (lane >> 2);
                int cb = wn + ((lane & 3) << 1);
#pragma unroll
                for (int ni = 0; ni < 4; ++ni) {
                    int c = cb + ni * 8;
                    float b0 = pb[h * DH + c], b1 = pb[h * DH + c + 1];
                    *reinterpret_cast<__half2*>(S + r * SROW + c) =
                        __floats2half2_rn(acc[ni][0] + b0, acc[ni][1] + b1);
                    *reinterpret_cast<__half2*>(S + (r + 8) * SROW + c) =
                        __floats2half2_rn(acc[ni][2] + b0, acc[ni][3] + b1);
                }
            }
        }
        __syncthreads();

        // ---- attention: 4 threads per row (row = tid>>2, qtr = tid&3) ----
        {
            int row = tid >> 2, qtr = tid & 3;
            int base = row & ~7, t = row & 7;
            const __half2* qp = reinterpret_cast<const __half2*>(Stg + row * SROW) + qtr * 8;
            __half2 q2[8];
#pragma unroll
            for (int j = 0; j < 8; ++j) q2[j] = qp[j];

            float sc[SEQT];
#pragma unroll
            for (int s = 0; s < SEQT; ++s) {
                const __half2* kp =
                    reinterpret_cast<const __half2*>(Stg + STG_STRIDE + (base + s) * SROW) + qtr * 8;
                float acl = 0.f;
#pragma unroll
                for (int j = 0; j < 8; ++j) {
                    __half2 p = __hmul2(q2[j], kp[j]);
                    acl += __low2float(p) + __high2float(p);
                }
                acl += __shfl_xor_sync(0xffffffffu, acl, 1);
                acl += __shfl_xor_sync(0xffffffffu, acl, 2);
                sc[s] = acl * 0.125f;   // 1/sqrt(64)
            }
            float m = sc[0];
#pragma unroll
            for (int s = 1; s < SEQT; ++s)
                if (s <= t && sc[s] > m) m = sc[s];
            float w[SEQT], sum = 0.f;
#pragma unroll
            for (int s = 0; s < SEQT; ++s) {
                w[s] = (s <= t) ? __expf(sc[s] - m) : 0.f;
                sum += w[s];
            }
            float inv = 1.f / sum;
            float o[16];
#pragma unroll
            for (int j = 0; j < 16; ++j) o[j] = 0.f;
#pragma unroll
            for (int s = 0; s < SEQT; ++s) {
                float ws = w[s] * inv;
                const __half2* vp =
                    reinterpret_cast<const __half2*>(Stg + 2 * STG_STRIDE + (base + s) * SROW) + qtr * 8;
#pragma unroll
                for (int j = 0; j < 8; ++j) {
                    __half2 v2 = vp[j];
                    o[2 * j]     += ws * __low2float(v2);
                    o[2 * j + 1] += ws * __high2float(v2);
                }
            }
            __half2* op = reinterpret_cast<__half2*>(Os + row * AROW + h * DH + qtr * 16);
#pragma unroll
            for (int j = 0; j < 8; ++j) op[j] = __floats2half2_rn(o[2 * j], o[2 * j + 1]);
        }
        __syncthreads();
    }

    // ---- output projection: Os[64,256] @ Wfc + bfc -> out (fp32) ----
    {
        uint32_t a[16][4];
        load_afrag(Os, wm, lane, a);
#pragma unroll
        for (int nc = 0; nc < 4; ++nc) {
            float acc[4][4];
#pragma unroll
            for (int ni = 0; ni < 4; ++ni)
#pragma unroll
                for (int c = 0; c < 4; ++c) acc[ni][c] = 0.f;
            gemm_reg(a, 12 + nc, wn, lane, acc);

            int r = wm + (lane >> 2);
            int cb = nc * 64 + wn + ((lane & 3) << 1);
#pragma unroll
            for (int ni = 0; ni < 4; ++ni) {
                int c = cb + ni * 8;
                float b0 = bfc[c], b1 = bfc[c + 1];
                *reinterpret_cast<float2*>(out + (row0 + r) * 256 + c) =
                    make_float2(acc[ni][0] + b0, acc[ni][1] + b1);
                *reinterpret_cast<float2*>(out + (row0 + r + 8) * 256 + c) =
                    make_float2(acc[ni][2] + b0, acc[ni][3] + b1);
            }
        }
    }
}

extern "C" void kernel_launch(void* const* d_in, const int* in_sizes, int n_in,
                              void* d_out, int out_size) {
    (void)in_sizes; (void)n_in; (void)out_size;
    const float* x   = (const float*)d_in[0];
    const float* Wq  = (const float*)d_in[1];
    const float* bq  = (const float*)d_in[2];
    const float* Wk  = (const float*)d_in[3];
    const float* bk  = (const float*)d_in[4];
    const float* Wv  = (const float*)d_in[5];
    const float* bv  = (const float*)d_in[6];
    const float* Wfc = (const float*)d_in[7];
    const float* bfc = (const float*)d_in[8];
    float* out = (float*)d_out;

    cudaFuncSetAttribute(attn_main, cudaFuncAttributeMaxDynamicSharedMemorySize, SMEM_BYTES);

    prep_frags<<<128, 256>>>(Wq, Wk, Wv, Wfc);
    attn_main<<<4096, 256, SMEM_BYTES>>>(x, bq, bk, bv, bfc, out);
}

// round 14
// speedup vs baseline: 1.5238x; 1.4794x over previous
#include <cuda_runtime.h>
#include <cuda_fp16.h>
#include <cstdint>

// Round 11: mma.sync path, loop-interchanged GEMMs. kt outer, chunks inner:
// one LDSM4 per kt feeds Q,K,V (or 2 FC) MMAs -> A-LDSM cut 256->96 per warp
// with only 4 A-regs live (no spills). B = uint4-packed fragments (LDG.128).
// M=64 tile, 8 warps (16 rows x 32 cols each), 2 CTAs/SM.

#define NHEADS 4
#define SEQT   8
#define DM     256
#define DH     64
#define MT     64
#define AROW   264                  // halves per row of Xs/Os (256+8 pad)
#define SROW   68                   // halves per row of qkv staging
#define STG_STRIDE (MT * SROW)
#define XS_HALVES  (MT * AROW)
#define STG_OFF    XS_HALVES
#define OS_OFF     (XS_HALVES + 3 * STG_STRIDE)
#define SMEM_HALVES (OS_OFF + MT * AROW)
#define SMEM_BYTES  (SMEM_HALVES * 2)   // 93696 B

// 16 chunks (12 QKV: cid=h*3+part; 4 FC: cid=12+nc), each [N=64, K=256].
// uint4 layout: [cid][kt(16)][j(4)][lane(32)], j = nt-pair; uint4 =
// {nt=2j: reg0, reg1, nt=2j+1: reg0, reg1} of mma m16n8k16 B fragments.
__device__ uint4 g_frag4[16 * 16 * 4 * 32];   // 512 KB

__global__ void prep_frags(const float* __restrict__ Wq, const float* __restrict__ Wk,
                           const float* __restrict__ Wv, const float* __restrict__ Wfc) {
    int g = blockIdx.x * 256 + threadIdx.x;          // 32768 threads
    int lane = g & 31, j = (g >> 5) & 3, kt = (g >> 7) & 15, cid = g >> 11;
    int n0 = j * 16 + (lane >> 2);                   // col of nt=2j
    int k0 = kt * 16 + ((lane & 3) << 1);
    float a0, a1, a2, a3, c0, c1, c2, c3;
    if (cid < 12) {
        int h = cid / 3, part = cid % 3;
        const float* W = (part == 0) ? Wq : ((part == 1) ? Wk : Wv);
        const float* p = W + h * DM * DH + n0;       // W[h][k][n], n-stride 1, k-stride DH
        a0 = p[k0 * DH];       a1 = p[(k0 + 1) * DH];
        a2 = p[(k0 + 8) * DH]; a3 = p[(k0 + 9) * DH];
        p += 8;
        c0 = p[k0 * DH];       c1 = p[(k0 + 1) * DH];
        c2 = p[(k0 + 8) * DH]; c3 = p[(k0 + 9) * DH];
    } else {
        int nc = cid - 12;
        const float* p = Wfc + nc * 64 + n0;         // Wfc[k][n], n-stride 1, k-stride 256
        a0 = p[k0 * 256];       a1 = p[(k0 + 1) * 256];
        a2 = p[(k0 + 8) * 256]; a3 = p[(k0 + 9) * 256];
        p += 8;
        c0 = p[k0 * 256];       c1 = p[(k0 + 1) * 256];
        c2 = p[(k0 + 8) * 256]; c3 = p[(k0 + 9) * 256];
    }
    __half2 l0 = __floats2half2_rn(a0, a1), h0 = __floats2half2_rn(a2, a3);
    __half2 l1 = __floats2half2_rn(c0, c1), h1 = __floats2half2_rn(c2, c3);
    uint4 v;
    v.x = *reinterpret_cast<uint32_t*>(&l0);
    v.y = *reinterpret_cast<uint32_t*>(&h0);
    v.z = *reinterpret_cast<uint32_t*>(&l1);
    v.w = *reinterpret_cast<uint32_t*>(&h1);
    g_frag4[g] = v;
}

#define LDSM4(R0, R1, R2, R3, ADDR)                                                \
    asm volatile("ldmatrix.sync.aligned.m8n8.x4.shared.b16 {%0,%1,%2,%3}, [%4];\n" \
                 : "=r"(R0), "=r"(R1), "=r"(R2), "=r"(R3)                          \
                 : "r"(ADDR))

#define MMA16816(D, A0, A1, A2, A3, B0, B1)                                        \
    asm volatile(                                                                  \
        "mma.sync.aligned.m16n8k16.row.col.f32.f16.f16.f32 "                       \
        "{%0,%1,%2,%3}, {%4,%5,%6,%7}, {%8,%9}, {%0,%1,%2,%3};\n"                  \
        : "+f"(D[0]), "+f"(D[1]), "+f"(D[2]), "+f"(D[3])                           \
        : "r"(A0), "r"(A1), "r"(A2), "r"(A3), "r"(B0), "r"(B1))

#define MMA_PAIR(ACC, F, KT)                                                       \
    do {                                                                           \
        uint4 B01 = (F)[((KT) * 4) * 32];                                          \
        uint4 B23 = (F)[((KT) * 4 + 1) * 32];                                      \
        MMA16816(ACC[0], a0, a1, a2, a3, B01.x, B01.y);                            \
        MMA16816(ACC[1], a0, a1, a2, a3, B01.z, B01.w);                            \
        MMA16816(ACC[2], a0, a1, a2, a3, B23.x, B23.y);                            \
        MMA16816(ACC[3], a0, a1, a2, a3, B23.z, B23.w);                            \
    } while (0)

#define ZERO_ACC(ACC)                                                              \
    _Pragma("unroll")                                                              \
    for (int ni = 0; ni < 4; ++ni)                                                 \
        _Pragma("unroll")                                                          \
        for (int cc = 0; cc < 4; ++cc) ACC[ni][cc] = 0.f;

__global__ __launch_bounds__(256, 2)
void attn_main(const float* __restrict__ x, const float* __restrict__ bq,
               const float* __restrict__ bk, const float* __restrict__ bv,
               const float* __restrict__ bfc, float* __restrict__ out) {
    extern __shared__ __half sm[];
    __half* Xs  = sm;             // [64][AROW]
    __half* Stg = sm + STG_OFF;   // 3 x [64][SROW]
    __half* Os  = sm + OS_OFF;    // [64][AROW]

    int tid = threadIdx.x, lane = tid & 31, wid = tid >> 5;
    int wm = (wid >> 1) * 16;     // 0,16,32,48
    int wn = (wid & 1) * 32;      // 0,32
    int row0 = blockIdx.x * MT;

    // ---- X tile: fp32 -> fp16 smem ----
#pragma unroll
    for (int i = tid; i < MT * 64; i += 256) {
        int r = i >> 6, c4 = i & 63;
        float4 v = reinterpret_cast<const float4*>(x)[(row0 + r) * 64 + c4];
        __half2* d = reinterpret_cast<__half2*>(Xs + r * AROW + c4 * 4);
        d[0] = __floats2half2_rn(v.x, v.y);
        d[1] = __floats2half2_rn(v.z, v.w);
    }
    __syncthreads();

    // A-operand ldmatrix addressing (same for every kt)
    uint32_t Abase = (uint32_t)__cvta_generic_to_shared(Xs);
    int arow = (((lane >> 3) & 1) << 3) + (lane & 7);
    int ak   = (lane >> 4) << 3;
    uint32_t AaddrX = Abase + (uint32_t)(((wm + arow) * AROW + ak) * 2);

    for (int h = 0; h < NHEADS; ++h) {
        // ---- fused QKV GEMM for head h: kt outer, 3 chunks inner ----
        float accQ[4][4], accK[4][4], accV[4][4];
        ZERO_ACC(accQ); ZERO_ACC(accK); ZERO_ACC(accV);
        {
            const uint4* fq = g_frag4 + ((h * 3 + 0) * 64 + (wn >> 4)) * 32 + lane;
            const uint4* fk = fq + 64 * 32;
            const uint4* fv = fk + 64 * 32;
#pragma unroll
            for (int kt = 0; kt < 16; ++kt) {
                uint32_t a0, a1, a2, a3;
                LDSM4(a0, a1, a2, a3, AaddrX + (uint32_t)(kt * 32));
                MMA_PAIR(accQ, fq, kt);
                MMA_PAIR(accK, fk, kt);
                MMA_PAIR(accV, fv, kt);
            }
        }
        // ---- epilogue: + bias, fp16, into staging ----
        {
            int r = wm + (lane >> 2);
            int cb = wn + ((lane & 3) << 1);
#pragma unroll
            for (int ni = 0; ni < 4; ++ni) {
                int c = cb + ni * 8;
                float q0 = bq[h * DH + c], q1 = bq[h * DH + c + 1];
                float k0 = bk[h * DH + c], k1 = bk[h * DH + c + 1];
                float v0 = bv[h * DH + c], v1 = bv[h * DH + c + 1];
                *reinterpret_cast<__half2*>(Stg + r * SROW + c) =
                    __floats2half2_rn(accQ[ni][0] + q0, accQ[ni][1] + q1);
                *reinterpret_cast<__half2*>(Stg + (r + 8) * SROW + c) =
                    __floats2half2_rn(accQ[ni][2] + q0, accQ[ni][3] + q1);
                *reinterpret_cast<__half2*>(Stg + STG_STRIDE + r * SROW + c) =
                    __floats2half2_rn(accK[ni][0] + k0, accK[ni][1] + k1);
                *reinterpret_cast<__half2*>(Stg + STG_STRIDE + (r + 8) * SROW + c) =
                    __floats2half2_rn(accK[ni][2] + k0, accK[ni][3] + k1);
                *reinterpret_cast<__half2*>(Stg + 2 * STG_STRIDE + r * SROW + c) =
                    __floats2half2_rn(accV[ni][0] + v0, accV[ni][1] + v1);
                *reinterpret_cast<__half2*>(Stg + 2 * STG_STRIDE + (r + 8) * SROW + c) =
                    __floats2half2_rn(accV[ni][2] + v0, accV[ni][3] + v1);
            }
        }
        __syncthreads();

        // ---- attention: 4 threads per row (row = tid>>2, qtr = tid&3) ----
        {
            int row = tid >> 2, qtr = tid & 3;
            int base = row & ~7, t = row & 7;
            const __half2* qp = reinterpret_cast<const __half2*>(Stg + row * SROW) + qtr * 8;
            __half2 q2[8];
#pragma unroll
            for (int j = 0; j < 8; ++j) q2[j] = qp[j];

            float sc[SEQT];
#pragma unroll
            for (int s = 0; s < SEQT; ++s) {
                const __half2* kp =
                    reinterpret_cast<const __half2*>(Stg + STG_STRIDE + (base + s) * SROW) + qtr * 8;
                float acl = 0.f;
#pragma unroll
                for (int j = 0; j < 8; ++j) {
                    __half2 p = __hmul2(q2[j], kp[j]);
                    acl += __low2float(p) + __high2float(p);
                }
                acl += __shfl_xor_sync(0xffffffffu, acl, 1);
                acl += __shfl_xor_sync(0xffffffffu, acl, 2);
                sc[s] = acl * 0.125f;   // 1/sqrt(64)
            }
            float m = sc[0];
#pragma unroll
            for (int s = 1; s < SEQT; ++s)
                if (s <= t && sc[s] > m) m = sc[s];
            float w[SEQT], sum = 0.f;
#pragma unroll
            for (int s = 0; s < SEQT; ++s) {
                w[s] = (s <= t) ? __expf(sc[s] - m) : 0.f;
                sum += w[s];
            }
            float inv = 1.f / sum;
            float o[16];
#pragma unroll
            for (int j = 0; j < 16; ++j) o[j] = 0.f;
#pragma unroll
            for (int s = 0; s < SEQT; ++s) {
                float ws = w[s] * inv;
                const __half2* vp =
                    reinterpret_cast<const __half2*>(Stg + 2 * STG_STRIDE + (base + s) * SROW) + qtr * 8;
#pragma unroll
                for (int j = 0; j < 8; ++j) {
                    __half2 v2 = vp[j];
                    o[2 * j]     += ws * __low2float(v2);
                    o[2 * j + 1] += ws * __high2float(v2);
                }
            }
            __half2* op = reinterpret_cast<__half2*>(Os + row * AROW + h * DH + qtr * 16);
#pragma unroll
            for (int j = 0; j < 8; ++j) op[j] = __floats2half2_rn(o[2 * j], o[2 * j + 1]);
        }
        __syncthreads();
    }

    // ---- output projection: Os[64,256] @ Wfc + bfc -> out (fp32) ----
    uint32_t AaddrO = Abase + (uint32_t)(((OS_OFF) + (wm + arow) * AROW + ak) * 2);
#pragma unroll
    for (int pass = 0; pass < 2; ++pass) {
        float accA[4][4], accB[4][4];
        ZERO_ACC(accA); ZERO_ACC(accB);
        {
            const uint4* fa = g_frag4 + ((12 + pass * 2) * 64 + (wn >> 4)) * 32 + lane;
            const uint4* fb = fa + 64 * 32;
#pragma unroll
            for (int kt = 0; kt < 16; ++kt) {
                uint32_t a0, a1, a2, a3;
                LDSM4(a0, a1, a2, a3, AaddrO + (uint32_t)(kt * 32));
                MMA_PAIR(accA, fa, kt);
                MMA_PAIR(accB, fb, kt);
            }
        }
        int r = wm + (lane >> 2);
#pragma unroll
        for (int half = 0; half < 2; ++half) {
            float (*acc)[4] = half ? accB : accA;
            int cb = (pass * 2 + half) * 64 + wn + ((lane & 3) << 1);
#pragma unroll
            for (int ni = 0; ni < 4; ++ni) {
                int c = cb + ni * 8;
                float b0 = bfc[c], b1 = bfc[c + 1];
                *reinterpret_cast<float2*>(out + (row0 + r) * 256 + c) =
                    make_float2(acc[ni][0] + b0, acc[ni][1] + b1);
                *reinterpret_cast<float2*>(out + (row0 + r + 8) * 256 + c) =
                    make_float2(acc[ni][2] + b0, acc[ni][3] + b1);
            }
        }
    }
}

extern "C" void kernel_launch(void* const* d_in, const int* in_sizes, int n_in,
                              void* d_out, int out_size) {
    (void)in_sizes; (void)n_in; (void)out_size;
    const float* x   = (const float*)d_in[0];
    const float* Wq  = (const float*)d_in[1];
    const float* bq  = (const float*)d_in[2];
    const float* Wk  = (const float*)d_in[3];
    const float* bk  = (const float*)d_in[4];
    const float* Wv  = (const float*)d_in[5];
    const float* bv  = (const float*)d_in[6];
    const float* Wfc = (const float*)d_in[7];
    const float* bfc = (const float*)d_in[8];
    float* out = (float*)d_out;

    cudaFuncSetAttribute(attn_main, cudaFuncAttributeMaxDynamicSharedMemorySize, SMEM_BYTES);

    prep_frags<<<128, 256>>>(Wq, Wk, Wv, Wfc);
    attn_main<<<4096, 256, SMEM_BYTES>>>(x, bq, bk, bv, bfc, out);
}